// round 10
// baseline (speedup 1.0000x reference)
#include <cuda_runtime.h>
#include <cuda_fp16.h>
#include <math.h>
#include <stdint.h>

// ---------------------------------------------------------------------------
// Mix_82360292868539 (R10): R8 + smem-staged coalesced epilogue store +
// single heterogeneous prep kernel (convert || subhist -> fused select,
// self-cleaning for graph replay).
// ---------------------------------------------------------------------------

#define N_ROWS 8192
#define KD 64
#define SUB 1024                        // subsample rows (stride 8)
#define NS ((unsigned long long)SUB * (unsigned long long)SUB)
#define NB_C 2048
#define COARSE_SCALE 4.0f
#define COARSE_W 0.25f

#define BT 128
#define KSB 144            // 128B row + 16B pad (conflict-free)
#define T_TILE (BT * KSB)              // 18432

// fused GEMM shared layout (bytes); stage buffer reuses [0, 33792)
#define SM_SX  0
#define SM_SY  512
#define SM_A   1024
#define SM_B   (SM_A + T_TILE)         // 19456
#define SM_TOT (SM_B + T_TILE)         // 37888
#define STG_PAD 132                    // stage row stride in floats

// prep kernel (subhist role) shared layout
#define LDS_ 132
#define SH_SMEM (2*KD*LDS_*(int)sizeof(float) + NB_C*(int)sizeof(unsigned int))

#define N_CONV_CTAS 2048
#define N_SUB_CTAS  ((SUB/128)*(SUB/128))   // 64

extern __shared__ char smem_raw[];

// ---- device scratch --------------------------------------------------------
__device__ __half g_xp[(size_t)N_ROWS * 64];     // hx, 1 MB
__device__ __half g_yp[(size_t)N_ROWS * 64];     // hy, 1 MB
__device__ float g_sqx[N_ROWS];
__device__ float g_sqy[N_ROWS];
__device__ unsigned int g_hist_c[NB_C];          // zero-init; self-cleaned
__device__ unsigned int g_done;                  // zero-init; self-cleaned
__device__ float g_inv2sigma;

// ---- ptx helpers -----------------------------------------------------------
__device__ __forceinline__ uint32_t smem_u32(const void* p) {
    uint32_t a;
    asm("{ .reg .u64 t; cvta.to.shared.u64 t, %1; cvt.u32.u64 %0, t; }"
        : "=r"(a) : "l"(p));
    return a;
}

#define LDSM_X4(r0, r1, r2, r3, addr) \
    asm volatile("ldmatrix.sync.aligned.m8n8.x4.shared.b16 {%0,%1,%2,%3}, [%4];" \
        : "=r"(r0), "=r"(r1), "=r"(r2), "=r"(r3) : "r"(addr))

#define MMA16816F(c, a, b0, b1) \
    asm volatile("mma.sync.aligned.m16n8k16.row.col.f32.f16.f16.f32 " \
        "{%0,%1,%2,%3}, {%4,%5,%6,%7}, {%8,%9}, {%0,%1,%2,%3};" \
        : "+f"((c)[0]), "+f"((c)[1]), "+f"((c)[2]), "+f"((c)[3]) \
        : "r"((a)[0]), "r"((a)[1]), "r"((a)[2]), "r"((a)[3]), "r"(b0), "r"(b1))

// ---------------------------------------------------------------------------
// prep: CTAs [0, 2048) convert (fp16 round + norms); CTAs [2048, 2112)
// subsample pdist histogram (independent: in-loop norms); last subhist CTA
// runs the interpolated median select and re-zeros scratch for graph replay.
// ---------------------------------------------------------------------------
__global__ void __launch_bounds__(256)
prep_kernel(const float* __restrict__ X, const float* __restrict__ Y) {
    const int tid = threadIdx.x;
    const int bid = blockIdx.x;

    if (bid < N_CONV_CTAS) {
        // ---- convert role ------------------------------------------------
        int gw = (bid * 256 + tid) >> 5;
        int lane = tid & 31;
        if (gw >= 2 * N_ROWS) return;
        int isx = (gw < N_ROWS) ? 1 : 0;
        int r = isx ? gw : gw - N_ROWS;
        const float2 v = ((const float2*)((isx ? X : Y) + (size_t)r * KD))[lane];
        float s = v.x * v.x + v.y * v.y;
        #pragma unroll
        for (int o = 16; o; o >>= 1) s += __shfl_xor_sync(0xffffffffu, s, o);
        __half2 h = __floats2half2_rn(v.x, v.y);
        ((__half2*)((isx ? g_xp : g_yp) + (size_t)r * 64))[lane] = h;
        if (lane == 0) { if (isx) g_sqx[r] = s; else g_sqy[r] = s; }
        return;
    }

    // ---- subhist role ----------------------------------------------------
    float* smem = (float*)smem_raw;
    float* As = smem;                                   // [64][LDS_]
    float* Bs = smem + KD * LDS_;
    unsigned int* sh = (unsigned int*)(smem + 2 * KD * LDS_);

    const int sid = bid - N_CONV_CTAS;
    const int bm = (sid >> 3) * 128;
    const int bn = (sid & 7) * 128;

    for (int i = tid; i < NB_C; i += 256) sh[i] = 0u;

    {
        const int c4 = tid >> 4;
        const int r0 = tid & 15;
        #pragma unroll
        for (int it = 0; it < 8; ++it) {
            int row = r0 + it * 16;
            const float4* Xr = (const float4*)(X + (size_t)(bm + row) * 8 * KD);
            const float4* Yr = (const float4*)(Y + (size_t)(bn + row) * 8 * KD);
            float4 v = Xr[c4];
            As[(c4 * 4 + 0) * LDS_ + row] = v.x;
            As[(c4 * 4 + 1) * LDS_ + row] = v.y;
            As[(c4 * 4 + 2) * LDS_ + row] = v.z;
            As[(c4 * 4 + 3) * LDS_ + row] = v.w;
            float4 w = Yr[c4];
            Bs[(c4 * 4 + 0) * LDS_ + row] = w.x;
            Bs[(c4 * 4 + 1) * LDS_ + row] = w.y;
            Bs[(c4 * 4 + 2) * LDS_ + row] = w.z;
            Bs[(c4 * 4 + 3) * LDS_ + row] = w.w;
        }
    }
    __syncthreads();

    const int tx = tid & 15, ty = tid >> 4;
    float acc[8][8];
    float sxr[8], syr[8];
    #pragma unroll
    for (int i = 0; i < 8; ++i) {
        sxr[i] = 0.0f; syr[i] = 0.0f;
        #pragma unroll
        for (int j = 0; j < 8; ++j) acc[i][j] = 0.0f;
    }

    #pragma unroll 8
    for (int k = 0; k < KD; ++k) {
        float4 a0 = *(const float4*)(As + k * LDS_ + ty * 8);
        float4 a1 = *(const float4*)(As + k * LDS_ + ty * 8 + 4);
        float4 b0 = *(const float4*)(Bs + k * LDS_ + tx * 8);
        float4 b1 = *(const float4*)(Bs + k * LDS_ + tx * 8 + 4);
        float a[8] = {a0.x, a0.y, a0.z, a0.w, a1.x, a1.y, a1.z, a1.w};
        float b[8] = {b0.x, b0.y, b0.z, b0.w, b1.x, b1.y, b1.z, b1.w};
        #pragma unroll
        for (int i = 0; i < 8; ++i) {
            sxr[i] = fmaf(a[i], a[i], sxr[i]);
            syr[i] = fmaf(b[i], b[i], syr[i]);
            #pragma unroll
            for (int j = 0; j < 8; ++j)
                acc[i][j] = fmaf(a[i], b[j], acc[i][j]);
        }
    }

    #pragma unroll
    for (int i = 0; i < 8; ++i)
        #pragma unroll
        for (int j = 0; j < 8; ++j) {
            float pd = sxr[i] + syr[j] - 2.0f * acc[i][j];
            int b = min(max((int)(pd * COARSE_SCALE), 0), NB_C - 1);
            atomicAdd(&sh[b], 1u);
        }

    __syncthreads();
    for (int i = tid; i < NB_C; i += 256) {
        unsigned int c = sh[i];
        if (c) atomicAdd(&g_hist_c[i], c);
    }

    // ---- last-CTA-done: fused select + scratch cleanup -------------------
    __shared__ unsigned int s_last;
    __threadfence();
    if (tid == 0) s_last = (atomicAdd(&g_done, 1u) == N_SUB_CTAS - 1u);
    __syncthreads();
    if (!s_last) return;

    __shared__ unsigned long long chunk[256];
    __shared__ float sv1, sv2;
    const int PER = NB_C / 256;
    unsigned long long s = 0;
    for (int u = 0; u < PER; ++u) s += g_hist_c[tid * PER + u];
    chunk[tid] = s;
    __syncthreads();
    #pragma unroll
    for (int off = 1; off < 256; off <<= 1) {
        unsigned long long add = (tid >= off) ? chunk[tid - off] : 0ull;
        __syncthreads();
        chunk[tid] += add;
        __syncthreads();
    }
    unsigned long long run = chunk[tid] - s;   // exclusive prefix
    const unsigned long long k1 = NS / 2 - 1, k2 = NS / 2;
    for (int u = 0; u < PER; ++u) {
        int b = tid * PER + u;
        unsigned long long c = g_hist_c[b];
        if (c) {
            if (k1 >= run && k1 < run + c)
                sv1 = ((float)b + ((float)(k1 - run) + 0.5f) / (float)c) * COARSE_W;
            if (k2 >= run && k2 < run + c)
                sv2 = ((float)b + ((float)(k2 - run) + 0.5f) / (float)c) * COARSE_W;
        }
        run += c;
    }
    __syncthreads();
    if (tid == 0) {
        float med = 0.5f * (sv1 + sv2);
        g_inv2sigma = logf((float)(N_ROWS + 1)) / med;
        g_done = 0u;                       // reset for next graph replay
    }
    for (int i = tid; i < NB_C; i += 256) g_hist_c[i] = 0u;
}

// ---------------------------------------------------------------------------
// fp16 HMMA GEMM, 128x128 CTA tile, 8 warps (2M x 4N), warp tile 64x32, K=64.
// Fused epilogue; output staged through smem for coalesced STG.128.
// ---------------------------------------------------------------------------
__global__ void __launch_bounds__(256, 2) gemm_fused_kernel(float* __restrict__ out) {
    char* smem = smem_raw;
    const uint32_t sb = smem_u32(smem);
    const int tid = threadIdx.x;
    const int wid = tid >> 5, lane = tid & 31;
    const int bm = blockIdx.y * BT, bn = blockIdx.x * BT;

    float* ssx = (float*)(smem + SM_SX);
    float* ssy = (float*)(smem + SM_SY);
    if (tid < BT) {
        ssx[tid] = g_sqx[bm + tid];
        ssy[tid] = g_sqy[bn + tid];
    }

    // A, B tiles: 128 rows x 8 uint4 each
    {
        const uint4* Ag = (const uint4*)(g_xp + (size_t)bm * 64);
        const uint4* Bg = (const uint4*)(g_yp + (size_t)bn * 64);
        #pragma unroll
        for (int it = 0; it < 4; ++it) {
            int i = tid + it * 256;        // 1024 uint4
            int r = i >> 3, c = i & 7;
            *(uint4*)(smem + SM_A + r * KSB + c * 16) = Ag[i];
            *(uint4*)(smem + SM_B + r * KSB + c * 16) = Bg[i];
        }
    }
    __syncthreads();

    const int wm = (wid & 1) * 64;
    const int wn = (wid >> 1) * 32;
    const int lrow = lane & 15;
    const int lcol = (lane >> 4) * 16;

    float acc[4][4][4];
    #pragma unroll
    for (int mt = 0; mt < 4; ++mt)
        #pragma unroll
        for (int nt = 0; nt < 4; ++nt)
            #pragma unroll
            for (int q = 0; q < 4; ++q) acc[mt][nt][q] = 0.0f;

    const uint32_t Abase = sb + SM_A + (wm + lrow) * KSB + lcol;
    const uint32_t Bbase = sb + SM_B + (wn + lrow) * KSB + lcol;

    #pragma unroll
    for (int kk = 0; kk < 4; ++kk) {       // 4 x k16 = K64
        const int kb = kk * 32;
        uint32_t b[2][4];
        #pragma unroll
        for (int np = 0; np < 2; ++np)
            LDSM_X4(b[np][0], b[np][1], b[np][2], b[np][3],
                    Bbase + np * (16 * KSB) + kb);
        uint32_t a[4][4];
        #pragma unroll
        for (int mt = 0; mt < 4; ++mt)
            LDSM_X4(a[mt][0], a[mt][1], a[mt][2], a[mt][3],
                    Abase + mt * (16 * KSB) + kb);
        #pragma unroll
        for (int mt = 0; mt < 4; ++mt)
            #pragma unroll
            for (int nt = 0; nt < 4; ++nt) {
                const int np = nt >> 1, h = nt & 1;
                MMA16816F(acc[mt][nt], a[mt], b[np][h], b[np][h + 2]);
            }
    }

    // preload norms to registers (smem gets overwritten by the stage buffer)
    const float inv2s = g_inv2sigma;
    const int qrow = lane >> 2;
    const int qcol = (lane & 3) * 2;
    float sxr[8], syr[8];
    #pragma unroll
    for (int mt = 0; mt < 4; ++mt) {
        sxr[mt * 2 + 0] = ssx[wm + mt * 16 + qrow];
        sxr[mt * 2 + 1] = ssx[wm + mt * 16 + qrow + 8];
    }
    #pragma unroll
    for (int nt = 0; nt < 4; ++nt) {
        syr[nt * 2 + 0] = ssy[wn + nt * 8 + qcol];
        syr[nt * 2 + 1] = ssy[wn + nt * 8 + qcol + 1];
    }
    __syncthreads();

    // staged epilogue: two 64-row passes through smem, coalesced STG.128 out
    float* stage = (float*)smem;           // [64][STG_PAD]
    #pragma unroll
    for (int p = 0; p < 2; ++p) {
        if ((wid & 1) == p) {
            #pragma unroll
            for (int mt = 0; mt < 4; ++mt) {
                #pragma unroll
                for (int rs = 0; rs < 2; ++rs) {
                    const int lr = mt * 16 + qrow + rs * 8;   // 0..63
                    const float sx = sxr[mt * 2 + rs];
                    #pragma unroll
                    for (int nt = 0; nt < 4; ++nt) {
                        const int col = wn + nt * 8 + qcol;
                        const float v0 = acc[mt][nt][rs * 2 + 0];
                        const float v1 = acc[mt][nt][rs * 2 + 1];
                        float r0 = __expf(-(sx + syr[nt * 2 + 0] - 2.0f * v0) * inv2s) + 0.1f * v0 * v0;
                        float r1 = __expf(-(sx + syr[nt * 2 + 1] - 2.0f * v1) * inv2s) + 0.1f * v1 * v1;
                        *(float2*)(stage + lr * STG_PAD + col) = make_float2(r0, r1);
                    }
                }
            }
        }
        __syncthreads();
        #pragma unroll
        for (int it = 0; it < 8; ++it) {
            int idx = tid + it * 256;      // 0..2047
            int r = idx >> 5, c4 = idx & 31;
            uint4 v = *(uint4*)(stage + r * STG_PAD + c4 * 4);
            *(uint4*)(out + (size_t)(bm + p * 64 + r) * N_ROWS + bn + c4 * 4) = v;
        }
        __syncthreads();
    }
}

// ---------------------------------------------------------------------------
extern "C" void kernel_launch(void* const* d_in, const int* in_sizes, int n_in,
                              void* d_out, int out_size) {
    const float* X = (const float*)d_in[0];
    const float* Y = (const float*)d_in[1];
    float* out = (float*)d_out;

    cudaFuncSetAttribute(gemm_fused_kernel, cudaFuncAttributeMaxDynamicSharedMemorySize,
                         SM_TOT);
    cudaFuncSetAttribute(prep_kernel, cudaFuncAttributeMaxDynamicSharedMemorySize,
                         SH_SMEM);

    prep_kernel<<<N_CONV_CTAS + N_SUB_CTAS, 256, SH_SMEM>>>(X, Y);
    gemm_fused_kernel<<<dim3(N_ROWS / BT, N_ROWS / BT), 256, SM_TOT>>>(out);
}

// round 11
// speedup vs baseline: 1.1526x; 1.1526x over previous
#include <cuda_runtime.h>
#include <cuda_fp16.h>
#include <math.h>
#include <stdint.h>

// ---------------------------------------------------------------------------
// Mix_82360292868539 (R11): R8 base + FULL-CTA smem-staged coalesced epilogue
// (all warps stage concurrently; one sync pair) + SUB=512 subhist with fused
// select. Convert kernel kept separate (R10 lesson).
// ---------------------------------------------------------------------------

#define N_ROWS 8192
#define KD 64
#define SUB 512                         // subsample rows (stride 16)
#define NS ((unsigned long long)SUB * (unsigned long long)SUB)
#define NB_C 2048
#define COARSE_SCALE 4.0f
#define COARSE_W 0.25f

#define BT 128
#define KSB 144            // 128B row + 16B pad (conflict-free)
#define T_TILE (BT * KSB)              // 18432

// fused GEMM shared layout (bytes); stage buffer overlays everything
#define SM_SX  0
#define SM_SY  512
#define SM_A   1024
#define SM_B   (SM_A + T_TILE)         // 19456
#define STG_PAD 132                    // stage row stride (floats)
#define SM_STAGE_TOT (BT * STG_PAD * 4)        // 67584
#define SM_TOT SM_STAGE_TOT

// subsample hist kernel shared layout
#define LDS_ 132
#define SH_SMEM (2*KD*LDS_*(int)sizeof(float) + NB_C*(int)sizeof(unsigned int))
#define N_SUB_CTAS ((SUB/128)*(SUB/128))       // 16

extern __shared__ char smem_raw[];

// ---- device scratch --------------------------------------------------------
__device__ __half g_xp[(size_t)N_ROWS * 64];     // hx, 1 MB
__device__ __half g_yp[(size_t)N_ROWS * 64];     // hy, 1 MB
__device__ float g_sqx[N_ROWS];
__device__ float g_sqy[N_ROWS];
__device__ unsigned int g_hist_c[NB_C];
__device__ unsigned int g_done;
__device__ float g_inv2sigma;

// ---- ptx helpers -----------------------------------------------------------
__device__ __forceinline__ uint32_t smem_u32(const void* p) {
    uint32_t a;
    asm("{ .reg .u64 t; cvta.to.shared.u64 t, %1; cvt.u32.u64 %0, t; }"
        : "=r"(a) : "l"(p));
    return a;
}

#define LDSM_X4(r0, r1, r2, r3, addr) \
    asm volatile("ldmatrix.sync.aligned.m8n8.x4.shared.b16 {%0,%1,%2,%3}, [%4];" \
        : "=r"(r0), "=r"(r1), "=r"(r2), "=r"(r3) : "r"(addr))

#define MMA16816F(c, a, b0, b1) \
    asm volatile("mma.sync.aligned.m16n8k16.row.col.f32.f16.f16.f32 " \
        "{%0,%1,%2,%3}, {%4,%5,%6,%7}, {%8,%9}, {%0,%1,%2,%3};" \
        : "+f"((c)[0]), "+f"((c)[1]), "+f"((c)[2]), "+f"((c)[3]) \
        : "r"((a)[0]), "r"((a)[1]), "r"((a)[2]), "r"((a)[3]), "r"(b0), "r"(b1))

// ---------------------------------------------------------------------------
// one warp per row: fp16 round + squared norm; first threads zero hist+flag
__global__ void convert_kernel(const float* __restrict__ X, const float* __restrict__ Y) {
    {
        int gi = blockIdx.x * blockDim.x + threadIdx.x;
        if (gi < NB_C) g_hist_c[gi] = 0u;
        if (gi == NB_C) g_done = 0u;
    }
    int gw = (blockIdx.x * blockDim.x + threadIdx.x) >> 5;
    int lane = threadIdx.x & 31;
    if (gw >= 2 * N_ROWS) return;
    int isx = (gw < N_ROWS) ? 1 : 0;
    int r = isx ? gw : gw - N_ROWS;
    const float2 v = ((const float2*)((isx ? X : Y) + (size_t)r * KD))[lane];
    float s = v.x * v.x + v.y * v.y;
    #pragma unroll
    for (int o = 16; o; o >>= 1) s += __shfl_xor_sync(0xffffffffu, s, o);

    __half2 h = __floats2half2_rn(v.x, v.y);
    ((__half2*)((isx ? g_xp : g_yp) + (size_t)r * 64))[lane] = h;
    if (lane == 0) { if (isx) g_sqx[r] = s; else g_sqy[r] = s; }
}

// ---------------------------------------------------------------------------
// Subsample pdist histogram (stride-16, exact fp32) + fused select (last CTA).
// ---------------------------------------------------------------------------
__global__ void __launch_bounds__(256)
subhist_kernel(const float* __restrict__ X, const float* __restrict__ Y) {
    float* smem = (float*)smem_raw;
    float* As = smem;                                   // [64][LDS_]
    float* Bs = smem + KD * LDS_;
    unsigned int* sh = (unsigned int*)(smem + 2 * KD * LDS_);

    const int tid = threadIdx.x;
    const int bm = blockIdx.y * 128;
    const int bn = blockIdx.x * 128;

    for (int i = tid; i < NB_C; i += 256) sh[i] = 0u;

    {
        const int c4 = tid >> 4;
        const int r0 = tid & 15;
        #pragma unroll
        for (int it = 0; it < 8; ++it) {
            int row = r0 + it * 16;
            const float4* Xr = (const float4*)(X + (size_t)(bm + row) * 16 * KD);
            const float4* Yr = (const float4*)(Y + (size_t)(bn + row) * 16 * KD);
            float4 v = Xr[c4];
            As[(c4 * 4 + 0) * LDS_ + row] = v.x;
            As[(c4 * 4 + 1) * LDS_ + row] = v.y;
            As[(c4 * 4 + 2) * LDS_ + row] = v.z;
            As[(c4 * 4 + 3) * LDS_ + row] = v.w;
            float4 w = Yr[c4];
            Bs[(c4 * 4 + 0) * LDS_ + row] = w.x;
            Bs[(c4 * 4 + 1) * LDS_ + row] = w.y;
            Bs[(c4 * 4 + 2) * LDS_ + row] = w.z;
            Bs[(c4 * 4 + 3) * LDS_ + row] = w.w;
        }
    }
    __syncthreads();

    const int tx = tid & 15, ty = tid >> 4;
    float acc[8][8];
    float sxr[8], syr[8];
    #pragma unroll
    for (int i = 0; i < 8; ++i) {
        sxr[i] = 0.0f; syr[i] = 0.0f;
        #pragma unroll
        for (int j = 0; j < 8; ++j) acc[i][j] = 0.0f;
    }

    #pragma unroll 8
    for (int k = 0; k < KD; ++k) {
        float4 a0 = *(const float4*)(As + k * LDS_ + ty * 8);
        float4 a1 = *(const float4*)(As + k * LDS_ + ty * 8 + 4);
        float4 b0 = *(const float4*)(Bs + k * LDS_ + tx * 8);
        float4 b1 = *(const float4*)(Bs + k * LDS_ + tx * 8 + 4);
        float a[8] = {a0.x, a0.y, a0.z, a0.w, a1.x, a1.y, a1.z, a1.w};
        float b[8] = {b0.x, b0.y, b0.z, b0.w, b1.x, b1.y, b1.z, b1.w};
        #pragma unroll
        for (int i = 0; i < 8; ++i) {
            sxr[i] = fmaf(a[i], a[i], sxr[i]);
            syr[i] = fmaf(b[i], b[i], syr[i]);
            #pragma unroll
            for (int j = 0; j < 8; ++j)
                acc[i][j] = fmaf(a[i], b[j], acc[i][j]);
        }
    }

    #pragma unroll
    for (int i = 0; i < 8; ++i)
        #pragma unroll
        for (int j = 0; j < 8; ++j) {
            float pd = sxr[i] + syr[j] - 2.0f * acc[i][j];
            int b = min(max((int)(pd * COARSE_SCALE), 0), NB_C - 1);
            atomicAdd(&sh[b], 1u);
        }

    __syncthreads();
    for (int i = tid; i < NB_C; i += 256) {
        unsigned int c = sh[i];
        if (c) atomicAdd(&g_hist_c[i], c);
    }

    // ---- last-CTA-done: fused select --------------------------------------
    __shared__ unsigned int s_last;
    __threadfence();
    if (tid == 0) s_last = (atomicAdd(&g_done, 1u) == N_SUB_CTAS - 1u);
    __syncthreads();
    if (!s_last) return;

    __shared__ unsigned long long chunk[256];
    __shared__ float sv1, sv2;
    const int PER = NB_C / 256;
    unsigned long long s = 0;
    for (int u = 0; u < PER; ++u) s += g_hist_c[tid * PER + u];
    chunk[tid] = s;
    __syncthreads();
    #pragma unroll
    for (int off = 1; off < 256; off <<= 1) {
        unsigned long long add = (tid >= off) ? chunk[tid - off] : 0ull;
        __syncthreads();
        chunk[tid] += add;
        __syncthreads();
    }
    unsigned long long run = chunk[tid] - s;   // exclusive prefix
    const unsigned long long k1 = NS / 2 - 1, k2 = NS / 2;
    for (int u = 0; u < PER; ++u) {
        int b = tid * PER + u;
        unsigned long long c = g_hist_c[b];
        if (c) {
            if (k1 >= run && k1 < run + c)
                sv1 = ((float)b + ((float)(k1 - run) + 0.5f) / (float)c) * COARSE_W;
            if (k2 >= run && k2 < run + c)
                sv2 = ((float)b + ((float)(k2 - run) + 0.5f) / (float)c) * COARSE_W;
        }
        run += c;
    }
    __syncthreads();
    if (tid == 0) {
        float med = 0.5f * (sv1 + sv2);
        g_inv2sigma = logf((float)(N_ROWS + 1)) / med;
    }
}

// ---------------------------------------------------------------------------
// fp16 HMMA GEMM, 128x128 CTA tile, 8 warps (2M x 4N), warp tile 64x32, K=64.
// Fused epilogue; ALL warps stage into [128][STG_PAD] smem, then coalesced
// STG.128 out. One sync pair, no warp idling.
// ---------------------------------------------------------------------------
__global__ void __launch_bounds__(256, 2) gemm_fused_kernel(float* __restrict__ out) {
    char* smem = smem_raw;
    const uint32_t sb = smem_u32(smem);
    const int tid = threadIdx.x;
    const int wid = tid >> 5, lane = tid & 31;
    const int bm = blockIdx.y * BT, bn = blockIdx.x * BT;

    float* ssx = (float*)(smem + SM_SX);
    float* ssy = (float*)(smem + SM_SY);
    if (tid < BT) {
        ssx[tid] = g_sqx[bm + tid];
        ssy[tid] = g_sqy[bn + tid];
    }

    // A, B tiles: 128 rows x 8 uint4 each
    {
        const uint4* Ag = (const uint4*)(g_xp + (size_t)bm * 64);
        const uint4* Bg = (const uint4*)(g_yp + (size_t)bn * 64);
        #pragma unroll
        for (int it = 0; it < 4; ++it) {
            int i = tid + it * 256;        // 1024 uint4
            int r = i >> 3, c = i & 7;
            *(uint4*)(smem + SM_A + r * KSB + c * 16) = Ag[i];
            *(uint4*)(smem + SM_B + r * KSB + c * 16) = Bg[i];
        }
    }
    __syncthreads();

    const int wm = (wid & 1) * 64;
    const int wn = (wid >> 1) * 32;
    const int lrow = lane & 15;
    const int lcol = (lane >> 4) * 16;

    float acc[4][4][4];
    #pragma unroll
    for (int mt = 0; mt < 4; ++mt)
        #pragma unroll
        for (int nt = 0; nt < 4; ++nt)
            #pragma unroll
            for (int q = 0; q < 4; ++q) acc[mt][nt][q] = 0.0f;

    const uint32_t Abase = sb + SM_A + (wm + lrow) * KSB + lcol;
    const uint32_t Bbase = sb + SM_B + (wn + lrow) * KSB + lcol;

    #pragma unroll
    for (int kk = 0; kk < 4; ++kk) {       // 4 x k16 = K64
        const int kb = kk * 32;
        uint32_t b[2][4];
        #pragma unroll
        for (int np = 0; np < 2; ++np)
            LDSM_X4(b[np][0], b[np][1], b[np][2], b[np][3],
                    Bbase + np * (16 * KSB) + kb);
        uint32_t a[4][4];
        #pragma unroll
        for (int mt = 0; mt < 4; ++mt)
            LDSM_X4(a[mt][0], a[mt][1], a[mt][2], a[mt][3],
                    Abase + mt * (16 * KSB) + kb);
        #pragma unroll
        for (int mt = 0; mt < 4; ++mt)
            #pragma unroll
            for (int nt = 0; nt < 4; ++nt) {
                const int np = nt >> 1, h = nt & 1;
                MMA16816F(acc[mt][nt], a[mt], b[np][h], b[np][h + 2]);
            }
    }

    // preload norms to registers (stage overwrites all smem)
    const float inv2s = g_inv2sigma;
    const int qrow = lane >> 2;
    const int qcol = (lane & 3) * 2;
    float sxr[8], syr[8];
    #pragma unroll
    for (int mt = 0; mt < 4; ++mt) {
        sxr[mt * 2 + 0] = ssx[wm + mt * 16 + qrow];
        sxr[mt * 2 + 1] = ssx[wm + mt * 16 + qrow + 8];
    }
    #pragma unroll
    for (int nt = 0; nt < 4; ++nt) {
        syr[nt * 2 + 0] = ssy[wn + nt * 8 + qcol];
        syr[nt * 2 + 1] = ssy[wn + nt * 8 + qcol + 1];
    }
    __syncthreads();

    // staged epilogue: all warps write their fragments into the stage buffer
    float* stage = (float*)smem;           // [128][STG_PAD]
    #pragma unroll
    for (int mt = 0; mt < 4; ++mt) {
        #pragma unroll
        for (int rs = 0; rs < 2; ++rs) {
            const int lr = wm + mt * 16 + qrow + rs * 8;
            const float sx = sxr[mt * 2 + rs];
            #pragma unroll
            for (int nt = 0; nt < 4; ++nt) {
                const int col = wn + nt * 8 + qcol;
                const float v0 = acc[mt][nt][rs * 2 + 0];
                const float v1 = acc[mt][nt][rs * 2 + 1];
                float r0 = __expf(-(sx + syr[nt * 2 + 0] - 2.0f * v0) * inv2s) + 0.1f * v0 * v0;
                float r1 = __expf(-(sx + syr[nt * 2 + 1] - 2.0f * v1) * inv2s) + 0.1f * v1 * v1;
                *(float2*)(stage + lr * STG_PAD + col) = make_float2(r0, r1);
            }
        }
    }
    __syncthreads();

    // coalesced writeback: 4096 uint4, 16 per thread
    #pragma unroll
    for (int it = 0; it < 16; ++it) {
        int idx = tid + it * 256;
        int r = idx >> 5, c4 = idx & 31;
        uint4 v = *(uint4*)(stage + r * STG_PAD + c4 * 4);
        *(uint4*)(out + (size_t)(bm + r) * N_ROWS + bn + c4 * 4) = v;
    }
}

// ---------------------------------------------------------------------------
extern "C" void kernel_launch(void* const* d_in, const int* in_sizes, int n_in,
                              void* d_out, int out_size) {
    const float* X = (const float*)d_in[0];
    const float* Y = (const float*)d_in[1];
    float* out = (float*)d_out;

    cudaFuncSetAttribute(gemm_fused_kernel, cudaFuncAttributeMaxDynamicSharedMemorySize,
                         SM_TOT);
    cudaFuncSetAttribute(subhist_kernel, cudaFuncAttributeMaxDynamicSharedMemorySize,
                         SH_SMEM);

    convert_kernel<<<(2 * N_ROWS * 32 + 255) / 256, 256>>>(X, Y);
    subhist_kernel<<<dim3(SUB / 128, SUB / 128), 256, SH_SMEM>>>(X, Y);
    gemm_fused_kernel<<<dim3(N_ROWS / BT, N_ROWS / BT), 256, SM_TOT>>>(out);
}

// round 12
// speedup vs baseline: 1.4952x; 1.2973x over previous
#include <cuda_runtime.h>
#include <cuda_fp16.h>
#include <math.h>
#include <stdint.h>

// ---------------------------------------------------------------------------
// Mix_82360292868539 (R12): R8 GEMM verbatim (plain epilogue — staging
// refuted twice) + single prep kernel with subhist CTAs FIRST (R10 inverted),
// fused select, self-cleaning scratch for graph replay.
// ---------------------------------------------------------------------------

#define N_ROWS 8192
#define KD 64
#define SUB 512                         // subsample rows (stride 16)
#define NS ((unsigned long long)SUB * (unsigned long long)SUB)
#define NB_C 2048
#define COARSE_SCALE 4.0f
#define COARSE_W 0.25f

#define BT 128
#define KSB 144            // 128B row + 16B pad (conflict-free)
#define T_TILE (BT * KSB)              // 18432

// fused GEMM shared layout (bytes)
#define SM_SX  0
#define SM_SY  512
#define SM_A   1024
#define SM_B   (SM_A + T_TILE)         // 19456
#define SM_TOT (SM_B + T_TILE)         // 37888

// prep kernel (subhist role) shared layout
#define LDS_ 132
#define SH_SMEM (2*KD*LDS_*(int)sizeof(float) + NB_C*(int)sizeof(unsigned int))

#define N_SUB_CTAS  ((SUB/128)*(SUB/128))   // 16 -> blocks [0, 16)
#define N_CONV_CTAS 2048                    // blocks [16, 2064)

extern __shared__ char smem_raw[];

// ---- device scratch (zero-init at load; self-cleaned each run) -------------
__device__ __half g_xp[(size_t)N_ROWS * 64];     // hx, 1 MB
__device__ __half g_yp[(size_t)N_ROWS * 64];     // hy, 1 MB
__device__ float g_sqx[N_ROWS];
__device__ float g_sqy[N_ROWS];
__device__ unsigned int g_hist_c[NB_C];
__device__ unsigned int g_done;
__device__ float g_inv2sigma;

// ---- ptx helpers -----------------------------------------------------------
__device__ __forceinline__ uint32_t smem_u32(const void* p) {
    uint32_t a;
    asm("{ .reg .u64 t; cvta.to.shared.u64 t, %1; cvt.u32.u64 %0, t; }"
        : "=r"(a) : "l"(p));
    return a;
}

#define LDSM_X4(r0, r1, r2, r3, addr) \
    asm volatile("ldmatrix.sync.aligned.m8n8.x4.shared.b16 {%0,%1,%2,%3}, [%4];" \
        : "=r"(r0), "=r"(r1), "=r"(r2), "=r"(r3) : "r"(addr))

#define MMA16816F(c, a, b0, b1) \
    asm volatile("mma.sync.aligned.m16n8k16.row.col.f32.f16.f16.f32 " \
        "{%0,%1,%2,%3}, {%4,%5,%6,%7}, {%8,%9}, {%0,%1,%2,%3};" \
        : "+f"((c)[0]), "+f"((c)[1]), "+f"((c)[2]), "+f"((c)[3]) \
        : "r"((a)[0]), "r"((a)[1]), "r"((a)[2]), "r"((a)[3]), "r"(b0), "r"(b1))

// ---------------------------------------------------------------------------
// prep: blocks [0,16) = subsample pdist histogram (own norms, stride 16) with
// fused select + scratch cleanup in the last-done CTA; blocks [16,2064) =
// fp16 convert + row norms (one warp per row). Heavy CTAs scheduled first.
// ---------------------------------------------------------------------------
__global__ void __launch_bounds__(256)
prep_kernel(const float* __restrict__ X, const float* __restrict__ Y) {
    const int tid = threadIdx.x;
    const int bid = blockIdx.x;

    if (bid >= N_SUB_CTAS) {
        // ---- convert role --------------------------------------------------
        int gw = ((bid - N_SUB_CTAS) * 256 + tid) >> 5;
        int lane = tid & 31;
        if (gw >= 2 * N_ROWS) return;
        int isx = (gw < N_ROWS) ? 1 : 0;
        int r = isx ? gw : gw - N_ROWS;
        const float2 v = ((const float2*)((isx ? X : Y) + (size_t)r * KD))[lane];
        float s = v.x * v.x + v.y * v.y;
        #pragma unroll
        for (int o = 16; o; o >>= 1) s += __shfl_xor_sync(0xffffffffu, s, o);
        __half2 h = __floats2half2_rn(v.x, v.y);
        ((__half2*)((isx ? g_xp : g_yp) + (size_t)r * 64))[lane] = h;
        if (lane == 0) { if (isx) g_sqx[r] = s; else g_sqy[r] = s; }
        return;
    }

    // ---- subhist role ------------------------------------------------------
    float* smem = (float*)smem_raw;
    float* As = smem;                                   // [64][LDS_]
    float* Bs = smem + KD * LDS_;
    unsigned int* sh = (unsigned int*)(smem + 2 * KD * LDS_);

    const int bm = (bid >> 2) * 128;
    const int bn = (bid & 3) * 128;

    for (int i = tid; i < NB_C; i += 256) sh[i] = 0u;

    {
        const int c4 = tid >> 4;
        const int r0 = tid & 15;
        #pragma unroll
        for (int it = 0; it < 8; ++it) {
            int row = r0 + it * 16;
            const float4* Xr = (const float4*)(X + (size_t)(bm + row) * 16 * KD);
            const float4* Yr = (const float4*)(Y + (size_t)(bn + row) * 16 * KD);
            float4 v = Xr[c4];
            As[(c4 * 4 + 0) * LDS_ + row] = v.x;
            As[(c4 * 4 + 1) * LDS_ + row] = v.y;
            As[(c4 * 4 + 2) * LDS_ + row] = v.z;
            As[(c4 * 4 + 3) * LDS_ + row] = v.w;
            float4 w = Yr[c4];
            Bs[(c4 * 4 + 0) * LDS_ + row] = w.x;
            Bs[(c4 * 4 + 1) * LDS_ + row] = w.y;
            Bs[(c4 * 4 + 2) * LDS_ + row] = w.z;
            Bs[(c4 * 4 + 3) * LDS_ + row] = w.w;
        }
    }
    __syncthreads();

    const int tx = tid & 15, ty = tid >> 4;
    float acc[8][8];
    float sxr[8], syr[8];
    #pragma unroll
    for (int i = 0; i < 8; ++i) {
        sxr[i] = 0.0f; syr[i] = 0.0f;
        #pragma unroll
        for (int j = 0; j < 8; ++j) acc[i][j] = 0.0f;
    }

    #pragma unroll 8
    for (int k = 0; k < KD; ++k) {
        float4 a0 = *(const float4*)(As + k * LDS_ + ty * 8);
        float4 a1 = *(const float4*)(As + k * LDS_ + ty * 8 + 4);
        float4 b0 = *(const float4*)(Bs + k * LDS_ + tx * 8);
        float4 b1 = *(const float4*)(Bs + k * LDS_ + tx * 8 + 4);
        float a[8] = {a0.x, a0.y, a0.z, a0.w, a1.x, a1.y, a1.z, a1.w};
        float b[8] = {b0.x, b0.y, b0.z, b0.w, b1.x, b1.y, b1.z, b1.w};
        #pragma unroll
        for (int i = 0; i < 8; ++i) {
            sxr[i] = fmaf(a[i], a[i], sxr[i]);
            syr[i] = fmaf(b[i], b[i], syr[i]);
            #pragma unroll
            for (int j = 0; j < 8; ++j)
                acc[i][j] = fmaf(a[i], b[j], acc[i][j]);
        }
    }

    #pragma unroll
    for (int i = 0; i < 8; ++i)
        #pragma unroll
        for (int j = 0; j < 8; ++j) {
            float pd = sxr[i] + syr[j] - 2.0f * acc[i][j];
            int b = min(max((int)(pd * COARSE_SCALE), 0), NB_C - 1);
            atomicAdd(&sh[b], 1u);
        }

    __syncthreads();
    for (int i = tid; i < NB_C; i += 256) {
        unsigned int c = sh[i];
        if (c) atomicAdd(&g_hist_c[i], c);
    }

    // ---- last-CTA-done: fused select + scratch cleanup --------------------
    __shared__ unsigned int s_last;
    __threadfence();
    if (tid == 0) s_last = (atomicAdd(&g_done, 1u) == N_SUB_CTAS - 1u);
    __syncthreads();
    if (!s_last) return;

    __shared__ unsigned long long chunk[256];
    __shared__ float sv1, sv2;
    const int PER = NB_C / 256;
    unsigned long long s = 0;
    for (int u = 0; u < PER; ++u) s += g_hist_c[tid * PER + u];
    chunk[tid] = s;
    __syncthreads();
    #pragma unroll
    for (int off = 1; off < 256; off <<= 1) {
        unsigned long long add = (tid >= off) ? chunk[tid - off] : 0ull;
        __syncthreads();
        chunk[tid] += add;
        __syncthreads();
    }
    unsigned long long run = chunk[tid] - s;   // exclusive prefix
    const unsigned long long k1 = NS / 2 - 1, k2 = NS / 2;
    for (int u = 0; u < PER; ++u) {
        int b = tid * PER + u;
        unsigned long long c = g_hist_c[b];
        if (c) {
            if (k1 >= run && k1 < run + c)
                sv1 = ((float)b + ((float)(k1 - run) + 0.5f) / (float)c) * COARSE_W;
            if (k2 >= run && k2 < run + c)
                sv2 = ((float)b + ((float)(k2 - run) + 0.5f) / (float)c) * COARSE_W;
        }
        run += c;
    }
    __syncthreads();
    if (tid == 0) {
        float med = 0.5f * (sv1 + sv2);
        g_inv2sigma = logf((float)(N_ROWS + 1)) / med;
        g_done = 0u;                       // reset for graph replay
    }
    for (int i = tid; i < NB_C; i += 256) g_hist_c[i] = 0u;
}

// ---------------------------------------------------------------------------
// fp16 HMMA GEMM, 128x128 CTA tile, 8 warps (2M x 4N), warp tile 64x32, K=64.
// Fused epilogue: out = exp(-pd*inv2s) + 0.1*inner^2.  (R8 verbatim.)
// ---------------------------------------------------------------------------
__global__ void __launch_bounds__(256, 2) gemm_fused_kernel(float* __restrict__ out) {
    char* smem = smem_raw;
    const uint32_t sb = smem_u32(smem);
    const int tid = threadIdx.x;
    const int wid = tid >> 5, lane = tid & 31;
    const int bm = blockIdx.y * BT, bn = blockIdx.x * BT;

    float* ssx = (float*)(smem + SM_SX);
    float* ssy = (float*)(smem + SM_SY);
    if (tid < BT) {
        ssx[tid] = g_sqx[bm + tid];
        ssy[tid] = g_sqy[bn + tid];
    }

    // A, B tiles: 128 rows x 8 uint4 each
    {
        const uint4* Ag = (const uint4*)(g_xp + (size_t)bm * 64);
        const uint4* Bg = (const uint4*)(g_yp + (size_t)bn * 64);
        #pragma unroll
        for (int it = 0; it < 4; ++it) {
            int i = tid + it * 256;        // 1024 uint4
            int r = i >> 3, c = i & 7;
            *(uint4*)(smem + SM_A + r * KSB + c * 16) = Ag[i];
            *(uint4*)(smem + SM_B + r * KSB + c * 16) = Bg[i];
        }
    }
    __syncthreads();

    const int wm = (wid & 1) * 64;
    const int wn = (wid >> 1) * 32;
    const int lrow = lane & 15;
    const int lcol = (lane >> 4) * 16;

    float acc[4][4][4];
    #pragma unroll
    for (int mt = 0; mt < 4; ++mt)
        #pragma unroll
        for (int nt = 0; nt < 4; ++nt)
            #pragma unroll
            for (int q = 0; q < 4; ++q) acc[mt][nt][q] = 0.0f;

    const uint32_t Abase = sb + SM_A + (wm + lrow) * KSB + lcol;
    const uint32_t Bbase = sb + SM_B + (wn + lrow) * KSB + lcol;

    #pragma unroll
    for (int kk = 0; kk < 4; ++kk) {       // 4 x k16 = K64
        const int kb = kk * 32;
        uint32_t b[2][4];
        #pragma unroll
        for (int np = 0; np < 2; ++np)
            LDSM_X4(b[np][0], b[np][1], b[np][2], b[np][3],
                    Bbase + np * (16 * KSB) + kb);
        uint32_t a[4][4];
        #pragma unroll
        for (int mt = 0; mt < 4; ++mt)
            LDSM_X4(a[mt][0], a[mt][1], a[mt][2], a[mt][3],
                    Abase + mt * (16 * KSB) + kb);
        #pragma unroll
        for (int mt = 0; mt < 4; ++mt)
            #pragma unroll
            for (int nt = 0; nt < 4; ++nt) {
                const int np = nt >> 1, h = nt & 1;
                MMA16816F(acc[mt][nt], a[mt], b[np][h], b[np][h + 2]);
            }
    }

    // fused epilogue
    const float inv2s = g_inv2sigma;
    const int qrow = lane >> 2;
    const int qcol = (lane & 3) * 2;
    #pragma unroll
    for (int mt = 0; mt < 4; ++mt) {
        #pragma unroll
        for (int rs = 0; rs < 2; ++rs) {
            const int row = wm + mt * 16 + qrow + rs * 8;
            const float sx = ssx[row];
            float* gout = out + (size_t)(bm + row) * N_ROWS + bn;
            #pragma unroll
            for (int nt = 0; nt < 4; ++nt) {
                const int col = wn + nt * 8 + qcol;
                const float v0 = acc[mt][nt][rs * 2 + 0];
                const float v1 = acc[mt][nt][rs * 2 + 1];
                float r0 = __expf(-(sx + ssy[col]     - 2.0f * v0) * inv2s) + 0.1f * v0 * v0;
                float r1 = __expf(-(sx + ssy[col + 1] - 2.0f * v1) * inv2s) + 0.1f * v1 * v1;
                *(float2*)(gout + col) = make_float2(r0, r1);
            }
        }
    }
}

// ---------------------------------------------------------------------------
extern "C" void kernel_launch(void* const* d_in, const int* in_sizes, int n_in,
                              void* d_out, int out_size) {
    const float* X = (const float*)d_in[0];
    const float* Y = (const float*)d_in[1];
    float* out = (float*)d_out;

    cudaFuncSetAttribute(gemm_fused_kernel, cudaFuncAttributeMaxDynamicSharedMemorySize,
                         SM_TOT);
    cudaFuncSetAttribute(prep_kernel, cudaFuncAttributeMaxDynamicSharedMemorySize,
                         SH_SMEM);

    prep_kernel<<<N_SUB_CTAS + N_CONV_CTAS, 256, SH_SMEM>>>(X, Y);
    gemm_fused_kernel<<<dim3(N_ROWS / BT, N_ROWS / BT), 256, SM_TOT>>>(out);
}